// round 12
// baseline (speedup 1.0000x reference)
#include <cuda_runtime.h>
#include <math.h>

typedef unsigned int u32;

#define BT 32768
#define HD 4096
#define GN 16
#define EPG 16
#define EN 256
#define KCH 64              // fp32 per K chunk (256 B per row)
#define NCHUNK 64           // 4096 / 64
#define TPB 288             // 8 consumer warps + 1 producer warp
#define TOKT 64
#define NP1 296             // producer CTAs (odd blockIdx), grid 592
#define NTILE1 (BT / TOKT)  // 512 phase-1 tiles
#define WTHR 32             // throttle window (>=16 required: pigeonhole)
#define THR1 2.5e-3f        // group-gap flag (1-mma tf32)
#define THR2 5e-3f          // expert-gap flag (1-mma tf32)

#define AW 68               // A row stride (words): 272 B, conflict-free frags
#define A_WORDS (TOKT * AW)          // 4352
#define WCH 1280            // W chunk words: [nbs(2)][lane(32)][20]
#define BUFW (A_WORDS + WCH)         // 5632 words = 22528 B
#define SBUF_BYTES (2 * BUFW * 4)    // 45056
#define SMEM_DYN (SBUF_BYTES + 1024) // 46080

#define N2WORDS (GN * NCHUNK * WCH)  // 1,310,720
#define N1WORDS (NCHUNK * WCH)       // 81,920
#define QCAP 2048

__device__ __align__(16) float g_w2[(size_t)N2WORDS]; // frag-major expert W (tf32-rn)
__device__ __align__(16) float g_w1[(size_t)N1WORDS]; // frag-major group W (tf32-rn)
__device__ int g_cnt[GN];
__device__ int g_bucket[GN][BT];
__device__ __align__(16) int g_tilecnt[GN * 512];
__device__ __align__(16) int q_entry[QCAP];
__device__ int g_qhead, g_qtail, g_qtotal;
__device__ int g_p1ticket, g_p1done, g_p2done;
__device__ int g_nfix;
__device__ int g_fix[BT];

// ---------------- primitives ----------------------------------------------------
__device__ __forceinline__ void mma8(float* c, const u32* a, u32 b0, u32 b1) {
    asm volatile(
        "mma.sync.aligned.m16n8k8.row.col.f32.tf32.tf32.f32 "
        "{%0,%1,%2,%3}, {%4,%5,%6,%7}, {%8,%9}, {%0,%1,%2,%3};"
        : "+f"(c[0]), "+f"(c[1]), "+f"(c[2]), "+f"(c[3])
        : "r"(a[0]), "r"(a[1]), "r"(a[2]), "r"(a[3]), "r"(b0), "r"(b1));
}
__device__ __forceinline__ u32 tf32rn(float v) {
    u32 r; asm("cvt.rna.tf32.f32 %0, %1;" : "=r"(r) : "f"(v)); return r;
}
__device__ __forceinline__ u32 fb(float v) { return __float_as_uint(v); }

__device__ __forceinline__ void mbar_init(u32 a, u32 n) {
    asm volatile("mbarrier.init.shared.b64 [%0], %1;" :: "r"(a), "r"(n) : "memory");
}
__device__ __forceinline__ void mbar_arrive(u32 a) {
    asm volatile("mbarrier.arrive.shared.b64 _, [%0];" :: "r"(a) : "memory");
}
__device__ __forceinline__ void mbar_expect(u32 a, u32 b) {
    asm volatile("mbarrier.arrive.expect_tx.shared.b64 _, [%0], %1;"
                 :: "r"(a), "r"(b) : "memory");
}
__device__ __forceinline__ void mbar_wait(u32 a, u32 ph) {
    asm volatile("{\n\t.reg .pred P;\n\tW_%=:\n\t"
        "mbarrier.try_wait.parity.shared::cta.b64 P, [%0], %1;\n\t"
        "@!P bra W_%=;\n\t}" :: "r"(a), "r"(ph) : "memory");
}
__device__ __forceinline__ void bulk_g2s(u32 dst, const void* src, u32 bytes, u32 mbar) {
    asm volatile("cp.async.bulk.shared::cta.global.mbarrier::complete_tx::bytes "
                 "[%0], [%1], %2, [%3];"
                 :: "r"(dst), "l"(src), "r"(bytes), "r"(mbar) : "memory");
}
#define FENCE_PA() asm volatile("fence.proxy.async.shared::cta;" ::: "memory")

// ---------------- prep: W -> fragment-major tf32-rn images + state zeroing ------
__global__ void prep_kernel(const float* __restrict__ gw, const float* __restrict__ ew) {
    u32 q = blockIdx.x * 256 + threadIdx.x;
    if (q < GN) g_cnt[q] = 0;
    else if (q == 16) g_nfix = 0;
    else if (q == 17) g_qhead = 0;
    else if (q == 18) g_qtail = 0;
    else if (q == 19) g_qtotal = -1;
    else if (q == 20) g_p1ticket = 0;
    else if (q == 21) g_p1done = 0;
    else if (q == 22) g_p2done = 0;

    const u32 Q2 = N2WORDS / 4, Q1 = N1WORDS / 4;
    if (q < Q2) {
        u32 w = q * 4;
        u32 g = w / (NCHUNK * WCH);
        u32 r = w - g * (NCHUNK * WCH);
        u32 chunk = r / WCH;  r -= chunk * WCH;
        u32 nbs = r / 640;    r -= nbs * 640;
        u32 lane = r / 20;
        u32 b = r - lane * 20;                  // 0,4,8,12,16
        float4 v = make_float4(0.f, 0.f, 0.f, 0.f);
        if (b < 16) {
            float* vp = (float*)&v;
            int row = g * EPG + nbs * 8 + (lane >> 2);
#pragma unroll
            for (int e = 0; e < 4; e++) {
                u32 widx = b + e, kk = widx >> 1, half = widx & 1;
                int col = chunk * KCH + kk * 8 + (lane & 3) + half * 4;
                vp[e] = __uint_as_float(tf32rn(ew[(size_t)row * HD + col]));
            }
        }
        *(float4*)&g_w2[w] = v;
    } else if (q < Q2 + Q1) {
        u32 w = (q - Q2) * 4;
        u32 chunk = w / WCH; u32 r = w - chunk * WCH;
        u32 nbs = r / 640;   r -= nbs * 640;
        u32 lane = r / 20;
        u32 b = r - lane * 20;
        float4 v = make_float4(0.f, 0.f, 0.f, 0.f);
        if (b < 16) {
            float* vp = (float*)&v;
            int row = nbs * 8 + (lane >> 2);
#pragma unroll
            for (int e = 0; e < 4; e++) {
                u32 widx = b + e, kk = widx >> 1, half = widx & 1;
                int col = chunk * KCH + kk * 8 + (lane & 3) + half * 4;
                vp[e] = __uint_as_float(tf32rn(gw[(size_t)row * HD + col]));
            }
        }
        *(float4*)&g_w1[w] = v;
    } else {
        u32 z = q - (Q2 + Q1);
        if (z < (GN * 512) / 4)
            *(int4*)&g_tilecnt[z * 4] = make_int4(0, 0, 0, 0);
        else if (z < (GN * 512) / 4 + QCAP / 4)
            *(int4*)&q_entry[(z - (GN * 512) / 4) * 4] = make_int4(0, 0, 0, 0);
    }
}

// ---------------- warp-specialized MMA tile core (single 1-mma mode) ------------
struct P1Tok { int t0; __device__ int operator()(int r) const { return t0 + r; } };
struct P2Tok { const int* s; __device__ int operator()(int r) const { return s[r]; } };

template <typename TOKF>
__device__ __forceinline__ void tile_mma(
    const float* __restrict__ hs, const float* __restrict__ wimg, TOKF tokof,
    float (*sbuf)[BUFW], u32 mb, float* acc, int* phf, int* phe)
{
    const int tid = threadIdx.x;
    const int lane = tid & 31, wid = tid >> 5;
    const u32 smb = (u32)__cvta_generic_to_shared(&sbuf[0][0]);
    const u32 fullb[2]  = { mb, mb + 8 };
    const u32 emptyb[2] = { mb + 16, mb + 24 };

    if (wid == 8) {
        const int r0 = lane, r1 = lane + 32;
        const int t0 = tokof(r0), t1 = tokof(r1);
        u32 b0 = __ballot_sync(0xFFFFFFFFu, t0 >= 0);
        u32 b1 = __ballot_sync(0xFFFFFFFFu, t1 >= 0);
        const u32 txbytes = (u32)(__popc(b0) + __popc(b1)) * (KCH * 4) + WCH * 4;
        FENCE_PA();
        for (int c = 0; c < NCHUNK; c++) {
            const int s = c & 1;
            mbar_wait(emptyb[s], phe[s]); phe[s] ^= 1;
            if (lane == 0) mbar_expect(fullb[s], txbytes);
            __syncwarp();
            const u32 base = smb + (u32)s * (BUFW * 4);
            if (t0 >= 0)
                bulk_g2s(base + r0 * (AW * 4), hs + (size_t)t0 * HD + c * KCH,
                         KCH * 4, fullb[s]);
            if (t1 >= 0)
                bulk_g2s(base + r1 * (AW * 4), hs + (size_t)t1 * HD + c * KCH,
                         KCH * 4, fullb[s]);
            if (lane == 0)
                bulk_g2s(base + A_WORDS * 4, wimg + (size_t)c * WCH,
                         WCH * 4, fullb[s]);
        }
    } else {
        const int lx = lane & 3, ly = lane >> 2;
        const int m0 = (wid >> 1) * 16;
        acc[0] = acc[1] = acc[2] = acc[3] = 0.f;
        for (int c = 0; c < NCHUNK; c++) {
            const int s = c & 1;
            mbar_wait(fullb[s], phf[s]); phf[s] ^= 1;
            const float* A = sbuf[s];
            const float* whf = A + A_WORDS + (wid & 1) * 640 + lane * 20;
#pragma unroll
            for (int j = 0; j < 4; j++) {
                float4 H = *(const float4*)(whf + j * 4);
#pragma unroll
                for (int p = 0; p < 2; p++) {
                    int kk = 2 * j + p;
                    int ra = (m0 + ly) * AW + kk * 8 + lx;
                    u32 a[4] = { fb(A[ra]), fb(A[ra + 8 * AW]),
                                 fb(A[ra + 4]), fb(A[ra + 8 * AW + 4]) };
                    mma8(acc, a, p ? fb(H.z) : fb(H.x), p ? fb(H.w) : fb(H.y));
                }
            }
            if (lane == 0) mbar_arrive(emptyb[s]);
        }
    }
    __syncthreads();
}

// stage acc -> sC[64][18]
__device__ __forceinline__ void stage_c(float* sC, const float* acc) {
    const int tid = threadIdx.x;
    const int lane = tid & 31, wid = tid >> 5;
    if (wid >= 8) return;
    const int lx = lane & 3, ly = lane >> 2;
    const int m0 = (wid >> 1) * 16, nb = (wid & 1) * 8;
    int row = m0 + ly, col = nb + 2 * lx;
    sC[row * 18 + col] = acc[0];       sC[row * 18 + col + 1] = acc[1];
    sC[(row + 8) * 18 + col] = acc[2]; sC[(row + 8) * 18 + col + 1] = acc[3];
}

// ---------------- fused persistent router ---------------------------------------
__global__ void __launch_bounds__(TPB, 4) fused_kernel(
    const float* __restrict__ hs, float* __restrict__ out)
{
    extern __shared__ char smem[];
    float (*sbuf)[BUFW] = reinterpret_cast<float(*)[BUFW]>(smem);
    const u32 mb = (u32)__cvta_generic_to_shared(smem) + SBUF_BYTES;
    int* sh    = (int*)(smem + SBUF_BYTES + 64);
    int* scnt  = sh;         // 16
    int* sbase = sh + 16;    // 16
    int* sbg   = sh + 32;    // 64
    int* sloff = sh + 96;    // 64
    int* stok  = sh + 160;   // 64
    int* spop  = sh + 224;   // 4

    const int tid = threadIdx.x;
    if (tid == 0) {
        mbar_init(mb, 1);      mbar_init(mb + 8, 1);     // full
        mbar_init(mb + 16, 8); mbar_init(mb + 24, 8);    // empty
        for (int i = 0; i < 8; i++) { mbar_arrive(mb + 16); mbar_arrive(mb + 24); }
        FENCE_PA();
    }
    __syncthreads();

    int phf[2] = {0, 0}, phe[2] = {0, 0};
    float acc[4];
    const size_t OSEL = (size_t)BT * EN, OWGT = OSEL + BT;

    if (blockIdx.x & 1) {
        // ---------------- producer role: phase-1 tiles -------------------------
        while (true) {
            if (tid == 0) spop[0] = atomicAdd(&g_p1ticket, 1);
            __syncthreads();
            const int t1 = spop[0];
            __syncthreads();
            if (t1 >= NTILE1) break;
            if (tid == 0)
                while (t1 - *(volatile int*)&g_p2done > WTHR) __nanosleep(256);
            __syncthreads();
            const int token0 = t1 * TOKT;

            tile_mma(hs, g_w1, P1Tok{token0}, sbuf, mb, acc, phf, phe);
            float* sC = &sbuf[0][0];
            stage_c(sC, acc);
            if (tid < GN) scnt[tid] = 0;
            __syncthreads();

            if (tid < TOKT) {
                const float* row = sC + tid * 18;
                float b1 = row[0], b2 = -1e30f; int bg = 0;
#pragma unroll
                for (int g = 1; g < GN; g++) {
                    float v = row[g];
                    if (v > b1) { b2 = b1; b1 = v; bg = g; }
                    else if (v > b2) b2 = v;
                }
                sbg[tid] = bg;
                sloff[tid] = atomicAdd(&scnt[bg], 1);
                if (b1 - b2 < THR1) g_fix[atomicAdd(&g_nfix, 1)] = token0 + tid;
            }
            __syncthreads();
            if (tid < GN) sbase[tid] = atomicAdd(&g_cnt[tid], scnt[tid]);
            __syncthreads();
            if (tid < TOKT)
                g_bucket[sbg[tid]][sbase[sbg[tid]] + sloff[tid]] = token0 + tid;
            __threadfence();
            __syncthreads();

            // per-tile completion counters -> publish ready phase-2 tiles
            if (tid < GN && scnt[tid] > 0) {
                int base = sbase[tid], n = scnt[tid];
                int ta = base >> 6, tb = (base + n - 1) >> 6;
                for (int tt = ta; tt <= tb; tt++) {
                    int lo = max(tt << 6, base), hi = min((tt + 1) << 6, base + n);
                    int k = hi - lo;
                    int old = atomicAdd(&g_tilecnt[tid * 512 + tt], k);
                    if (old + k == 64) {
                        int s = atomicAdd(&g_qtail, 1);
                        __threadfence();
                        q_entry[s] = ((tid << 9) | tt) + 1;
                    }
                }
            }
            __syncthreads();
        }
        if (tid == 0) {
            __threadfence();
            int d = atomicAdd(&g_p1done, 1);
            if (d + 1 == NP1) {
                __threadfence();
                for (int g = 0; g < GN; g++) {
                    int cnt = atomicAdd(&g_cnt[g], 0);
                    int r = cnt & 63;
                    if (r) {
                        int t = cnt >> 6;
                        for (int i = cnt; i < (t + 1) * 64; i++) g_bucket[g][i] = -1;
                        __threadfence();
                        int s = atomicAdd(&g_qtail, 1);
                        __threadfence();
                        q_entry[s] = ((g << 9) | t) + 1;
                    }
                }
                __threadfence();
                *(volatile int*)&g_qtotal = *(volatile int*)&g_qtail;
            }
        }
        __syncthreads();
    }

    // ---------------- consumer role: phase-2 tiles (everyone eventually) --------
    while (true) {
        if (tid == 0) {
            int h = atomicAdd(&g_qhead, 1);
            int e;
            while (true) {
                e = (h < QCAP) ? *(volatile int*)&q_entry[h] : 0;
                if (e) break;
                int qt = *(volatile int*)&g_qtotal;
                if (qt >= 0 && h >= qt) break;
                __nanosleep(128);
            }
            spop[0] = e;
        }
        __syncthreads();
        const int e = spop[0];
        __syncthreads();
        if (!e) break;
        __threadfence();
        const int g = (e - 1) >> 9, t = (e - 1) & 511;

        if (tid < TOKT) stok[tid] = g_bucket[g][t * 64 + tid];
        __syncthreads();

        tile_mma(hs, g_w2 + (size_t)g * (NCHUNK * WCH), P2Tok{stok},
                 sbuf, mb, acc, phf, phe);
        float* sC = &sbuf[0][0];
        stage_c(sC, acc);
        __syncthreads();

        if (tid < TOKT && stok[tid] >= 0) {
            const float* row = sC + tid * 18;
            float m1 = row[0], m2 = -1e30f; int bi = 0;
#pragma unroll
            for (int ee = 1; ee < EPG; ee++) {
                float v = row[ee];
                if (v > m1) { m2 = m1; m1 = v; bi = ee; }
                else if (v > m2) m2 = v;
            }
            float s = 0.f;
#pragma unroll
            for (int ee = 0; ee < EPG; ee++) s += expf(row[ee] - m1);
            int token = stok[tid];
            out[OSEL + token] = (float)(g * EPG + bi);
            out[OWGT + token] = 1.0f / s;
            if (m1 - m2 < THR2) g_fix[atomicAdd(&g_nfix, 1)] = token;
        }
        __syncthreads();

        if (tid < 256) {
            const int slot0 = tid >> 6, th = tid & 63;
#pragma unroll 4
            for (int p = 0; p < 16; p++) {
                int slot = p * 4 + slot0;
                int token = stok[slot];
                if (token >= 0) {
                    float4 v = make_float4(0.f, 0.f, 0.f, 0.f);
                    if ((th >> 2) == g) {
                        const float* row = sC + slot * 18 + (th & 3) * 4;
                        v = make_float4(row[0], row[1], row[2], row[3]);
                    }
                    *(float4*)&out[(size_t)token * EN + th * 4] = v;
                }
            }
        }
        if (tid == 0) atomicAdd(&g_p2done, 1);
        __syncthreads();
    }
}

// ---------------- exact fp32 fixup ----------------------------------------------
__global__ void __launch_bounds__(512) fixup_kernel(
    const float* __restrict__ hs, const float* __restrict__ gw,
    const float* __restrict__ ew, float* __restrict__ out)
{
    __shared__ float sg[GN], se[EPG];
    __shared__ int sbg_s;
    const int tid = threadIdx.x;
    const int wid = tid >> 5, lane = tid & 31;
    const size_t OSEL = (size_t)BT * EN, OWGT = OSEL + BT;
    const int n = g_nfix;

    for (int i = blockIdx.x; i < n; i += gridDim.x) {
        const int token = g_fix[i];
        const float4* x = (const float4*)(hs + (size_t)token * HD);
        {
            const float4* w = (const float4*)(gw + (size_t)wid * HD);
            float s = 0.f;
#pragma unroll 8
            for (int j = lane; j < HD / 4; j += 32) {
                float4 a = x[j], b = w[j];
                s += a.x * b.x + a.y * b.y + a.z * b.z + a.w * b.w;
            }
#pragma unroll
            for (int o = 16; o; o >>= 1) s += __shfl_xor_sync(0xFFFFFFFF, s, o);
            if (lane == 0) sg[wid] = s;
        }
        __syncthreads();
        if (tid == 0) {
            float best = sg[0]; int bg = 0;
#pragma unroll
            for (int g = 1; g < GN; g++) if (sg[g] > best) { best = sg[g]; bg = g; }
            sbg_s = bg;
        }
        __syncthreads();
        const int bg = sbg_s;
        {
            const float4* w = (const float4*)(ew + (size_t)(bg * EPG + wid) * HD);
            float s = 0.f;
#pragma unroll 8
            for (int j = lane; j < HD / 4; j += 32) {
                float4 a = x[j], b = w[j];
                s += a.x * b.x + a.y * b.y + a.z * b.z + a.w * b.w;
            }
#pragma unroll
            for (int o = 16; o; o >>= 1) s += __shfl_xor_sync(0xFFFFFFFF, s, o);
            if (lane == 0) se[wid] = s;
        }
        __syncthreads();
        if (tid == 0) {
            float m = se[0]; int bi = 0;
#pragma unroll
            for (int e = 1; e < EPG; e++) if (se[e] > m) { m = se[e]; bi = e; }
            float s = 0.f;
#pragma unroll
            for (int e = 0; e < EPG; e++) s += expf(se[e] - m);
            out[OSEL + token] = (float)(bg * EPG + bi);
            out[OWGT + token] = 1.0f / s;
        }
        if (tid < 64) {
            float4 v = make_float4(0.f, 0.f, 0.f, 0.f);
            if ((tid >> 2) == bg) {
                int lo = (tid & 3) * 4;
                v = make_float4(se[lo], se[lo + 1], se[lo + 2], se[lo + 3]);
            }
            *(float4*)&out[(size_t)token * EN + tid * 4] = v;
        }
        __syncthreads();
    }
}

extern "C" void kernel_launch(void* const* d_in, const int* in_sizes, int n_in,
                              void* d_out, int out_size) {
    const float* hs = (const float*)d_in[0];   // [32768, 4096]
    const float* gw = (const float*)d_in[1];   // [16, 4096]
    const float* ew = (const float*)d_in[2];   // [16, 16, 4096]
    float* out = (float*)d_out;

    cudaFuncSetAttribute(fused_kernel,
                         cudaFuncAttributeMaxDynamicSharedMemorySize, SMEM_DYN);

    prep_kernel<<<1370, 256>>>(gw, ew);
    fused_kernel<<<2 * NP1, TPB, SMEM_DYN>>>(hs, out);
    fixup_kernel<<<256, 512>>>(hs, gw, ew, out);
}

// round 13
// speedup vs baseline: 17.9174x; 17.9174x over previous
#include <cuda_runtime.h>
#include <math.h>

typedef unsigned int u32;

#define BT 32768
#define HD 4096
#define GN 16
#define EPG 16
#define EN 256
#define KCH 64              // fp32 per K chunk (256 B per row)
#define NCHUNK 64           // 4096 / 64
#define TPB 288             // 8 consumer warps + 1 producer warp
#define TOKT 64
#define P2Y 37              // 16*37 = 592 CTAs = one full wave at occ 4
#define THR1 2.5e-3f        // group-gap flag (1-mma tf32)
#define THR2 2.5e-3f        // expert-gap flag (1-mma tf32)

#define AW 68               // A row stride (words): 272 B, conflict-free frags
#define A_WORDS (TOKT * AW)          // 4352
#define WCH 1280            // W chunk words: [nbs(2)][lane(32)][20]
#define BUFW (A_WORDS + WCH)         // 5632 words = 22528 B
#define SBUF_BYTES (2 * BUFW * 4)    // 45056
#define SMEM_DYN (SBUF_BYTES + 1024) // 46080

#define N2WORDS (GN * NCHUNK * WCH)  // 1,310,720
#define N1WORDS (NCHUNK * WCH)       // 81,920

__device__ __align__(16) float g_w2[(size_t)N2WORDS]; // frag-major expert W (tf32-rn)
__device__ __align__(16) float g_w1[(size_t)N1WORDS]; // frag-major group W (tf32-rn)
__device__ int g_cnt[GN];
__device__ int g_bucket[GN][BT];
__device__ int g_nfix;
__device__ int g_fix[BT];

// ---------------- primitives ----------------------------------------------------
__device__ __forceinline__ void mma8(float* c, const u32* a, u32 b0, u32 b1) {
    asm volatile(
        "mma.sync.aligned.m16n8k8.row.col.f32.tf32.tf32.f32 "
        "{%0,%1,%2,%3}, {%4,%5,%6,%7}, {%8,%9}, {%0,%1,%2,%3};"
        : "+f"(c[0]), "+f"(c[1]), "+f"(c[2]), "+f"(c[3])
        : "r"(a[0]), "r"(a[1]), "r"(a[2]), "r"(a[3]), "r"(b0), "r"(b1));
}
__device__ __forceinline__ u32 tf32rn(float v) {
    u32 r; asm("cvt.rna.tf32.f32 %0, %1;" : "=r"(r) : "f"(v)); return r;
}
__device__ __forceinline__ u32 fb(float v) { return __float_as_uint(v); }

__device__ __forceinline__ void mbar_init(u32 a, u32 n) {
    asm volatile("mbarrier.init.shared.b64 [%0], %1;" :: "r"(a), "r"(n) : "memory");
}
__device__ __forceinline__ void mbar_arrive(u32 a) {
    asm volatile("mbarrier.arrive.shared.b64 _, [%0];" :: "r"(a) : "memory");
}
__device__ __forceinline__ void mbar_expect(u32 a, u32 b) {
    asm volatile("mbarrier.arrive.expect_tx.shared.b64 _, [%0], %1;"
                 :: "r"(a), "r"(b) : "memory");
}
__device__ __forceinline__ void mbar_wait(u32 a, u32 ph) {
    asm volatile("{\n\t.reg .pred P;\n\tW_%=:\n\t"
        "mbarrier.try_wait.parity.shared::cta.b64 P, [%0], %1;\n\t"
        "@!P bra W_%=;\n\t}" :: "r"(a), "r"(ph) : "memory");
}
__device__ __forceinline__ void bulk_g2s(u32 dst, const void* src, u32 bytes, u32 mbar) {
    asm volatile("cp.async.bulk.shared::cta.global.mbarrier::complete_tx::bytes "
                 "[%0], [%1], %2, [%3];"
                 :: "r"(dst), "l"(src), "r"(bytes), "r"(mbar) : "memory");
}
#define FENCE_PA() asm volatile("fence.proxy.async.shared::cta;" ::: "memory")

// ---------------- prep: W -> fragment-major tf32-rn images ----------------------
// layout: [g][chunk][nbs(2)][lane(32)][20]; words 0..15 hold frag pairs
// {W[nbs*8+ly][8kk+lx], W[..][8kk+lx+4]} kk=0..7; words 16..19 pad (80 B stride).
__global__ void prep_kernel(const float* __restrict__ gw, const float* __restrict__ ew) {
    u32 q = blockIdx.x * 256 + threadIdx.x;
    if (q < GN) g_cnt[q] = 0;
    if (q == GN) g_nfix = 0;
    const u32 Q2 = N2WORDS / 4, Q1 = N1WORDS / 4;
    if (q < Q2) {
        u32 w = q * 4;
        u32 g = w / (NCHUNK * WCH);
        u32 r = w - g * (NCHUNK * WCH);
        u32 chunk = r / WCH;  r -= chunk * WCH;
        u32 nbs = r / 640;    r -= nbs * 640;
        u32 lane = r / 20;
        u32 b = r - lane * 20;                  // 0,4,8,12,16
        float4 v = make_float4(0.f, 0.f, 0.f, 0.f);
        if (b < 16) {
            float* vp = (float*)&v;
            int row = g * EPG + nbs * 8 + (lane >> 2);
#pragma unroll
            for (int e = 0; e < 4; e++) {
                u32 widx = b + e, kk = widx >> 1, half = widx & 1;
                int col = chunk * KCH + kk * 8 + (lane & 3) + half * 4;
                vp[e] = __uint_as_float(tf32rn(ew[(size_t)row * HD + col]));
            }
        }
        *(float4*)&g_w2[w] = v;
    } else if (q < Q2 + Q1) {
        u32 w = (q - Q2) * 4;
        u32 chunk = w / WCH; u32 r = w - chunk * WCH;
        u32 nbs = r / 640;   r -= nbs * 640;
        u32 lane = r / 20;
        u32 b = r - lane * 20;
        float4 v = make_float4(0.f, 0.f, 0.f, 0.f);
        if (b < 16) {
            float* vp = (float*)&v;
            int row = nbs * 8 + (lane >> 2);
#pragma unroll
            for (int e = 0; e < 4; e++) {
                u32 widx = b + e, kk = widx >> 1, half = widx & 1;
                int col = chunk * KCH + kk * 8 + (lane & 3) + half * 4;
                vp[e] = __uint_as_float(tf32rn(gw[(size_t)row * HD + col]));
            }
        }
        *(float4*)&g_w1[w] = v;
    }
}

// ---------------- warp-specialized MMA tile core (1-mma plain tf32) -------------
struct P1Tok { int t0; __device__ int operator()(int r) const { return t0 + r; } };
struct P2Tok { const int* s; __device__ int operator()(int r) const { return s[r]; } };

template <typename TOKF>
__device__ __forceinline__ void tile_mma(
    const float* __restrict__ hs, const float* __restrict__ wimg, TOKF tokof,
    float (*sbuf)[BUFW], u32 mb, float* acc, int* phf, int* phe)
{
    const int tid = threadIdx.x;
    const int lane = tid & 31, wid = tid >> 5;
    const u32 smb = (u32)__cvta_generic_to_shared(&sbuf[0][0]);
    const u32 fullb[2]  = { mb, mb + 8 };
    const u32 emptyb[2] = { mb + 16, mb + 24 };

    if (wid == 8) {
        const int r0 = lane, r1 = lane + 32;
        const int t0 = tokof(r0), t1 = tokof(r1);
        u32 b0 = __ballot_sync(0xFFFFFFFFu, t0 >= 0);
        u32 b1 = __ballot_sync(0xFFFFFFFFu, t1 >= 0);
        const u32 txbytes = (u32)(__popc(b0) + __popc(b1)) * (KCH * 4) + WCH * 4;
        FENCE_PA();
        for (int c = 0; c < NCHUNK; c++) {
            const int s = c & 1;
            mbar_wait(emptyb[s], phe[s]); phe[s] ^= 1;
            if (lane == 0) mbar_expect(fullb[s], txbytes);
            __syncwarp();
            const u32 base = smb + (u32)s * (BUFW * 4);
            if (t0 >= 0)
                bulk_g2s(base + r0 * (AW * 4), hs + (size_t)t0 * HD + c * KCH,
                         KCH * 4, fullb[s]);
            if (t1 >= 0)
                bulk_g2s(base + r1 * (AW * 4), hs + (size_t)t1 * HD + c * KCH,
                         KCH * 4, fullb[s]);
            if (lane == 0)
                bulk_g2s(base + A_WORDS * 4, wimg + (size_t)c * WCH,
                         WCH * 4, fullb[s]);
        }
    } else {
        const int lx = lane & 3, ly = lane >> 2;
        const int m0 = (wid >> 1) * 16;
        acc[0] = acc[1] = acc[2] = acc[3] = 0.f;
        for (int c = 0; c < NCHUNK; c++) {
            const int s = c & 1;
            mbar_wait(fullb[s], phf[s]); phf[s] ^= 1;
            const float* A = sbuf[s];
            const float* whf = A + A_WORDS + (wid & 1) * 640 + lane * 20;
#pragma unroll
            for (int j = 0; j < 4; j++) {
                float4 H = *(const float4*)(whf + j * 4);
#pragma unroll
                for (int p = 0; p < 2; p++) {
                    int kk = 2 * j + p;
                    int ra = (m0 + ly) * AW + kk * 8 + lx;
                    u32 a[4] = { fb(A[ra]), fb(A[ra + 8 * AW]),
                                 fb(A[ra + 4]), fb(A[ra + 8 * AW + 4]) };
                    mma8(acc, a, p ? fb(H.z) : fb(H.x), p ? fb(H.w) : fb(H.y));
                }
            }
            if (lane == 0) mbar_arrive(emptyb[s]);
        }
    }
    __syncthreads();
}

__device__ __forceinline__ void barriers_setup(u32 mb, int tid) {
    if (tid == 0) {
        mbar_init(mb, 1);      mbar_init(mb + 8, 1);     // full: expect-arrive
        mbar_init(mb + 16, 8); mbar_init(mb + 24, 8);    // empty: 8 warp arrives
        for (int i = 0; i < 8; i++) { mbar_arrive(mb + 16); mbar_arrive(mb + 24); }
        FENCE_PA();
    }
}

// stage acc -> sC[64][18]
__device__ __forceinline__ void stage_c(float* sC, const float* acc) {
    const int tid = threadIdx.x;
    const int lane = tid & 31, wid = tid >> 5;
    if (wid >= 8) return;
    const int lx = lane & 3, ly = lane >> 2;
    const int m0 = (wid >> 1) * 16, nb = (wid & 1) * 8;
    int row = m0 + ly, col = nb + 2 * lx;
    sC[row * 18 + col] = acc[0];       sC[row * 18 + col + 1] = acc[1];
    sC[(row + 8) * 18 + col] = acc[2]; sC[(row + 8) * 18 + col + 1] = acc[3];
}

// ---------------- phase 1: group logits, argmax, bucketing ---------------------
__global__ void __launch_bounds__(TPB) phase1_kernel(const float* __restrict__ hs)
{
    extern __shared__ char smem[];
    float (*sbuf)[BUFW] = reinterpret_cast<float(*)[BUFW]>(smem);
    const u32 mb = (u32)__cvta_generic_to_shared(smem) + SBUF_BYTES;
    int* si = (int*)(smem + SBUF_BYTES + 64);
    int* scnt = si;        // 16
    int* sbase = si + 16;  // 16
    int* sbg = si + 32;    // 64
    int* sloff = si + 96;  // 64

    const int tid = threadIdx.x;
    const int token0 = blockIdx.x * TOKT;

    barriers_setup(mb, tid);
    __syncthreads();

    int phf[2] = {0, 0}, phe[2] = {0, 0};
    float acc[4];
    tile_mma(hs, g_w1, P1Tok{token0}, sbuf, mb, acc, phf, phe);

    float* sC = &sbuf[0][0];
    stage_c(sC, acc);
    if (tid < GN) scnt[tid] = 0;
    __syncthreads();

    if (tid < TOKT) {
        const float* row = sC + tid * 18;
        float b1 = row[0], b2 = -1e30f; int bg = 0;
#pragma unroll
        for (int g = 1; g < GN; g++) {
            float v = row[g];
            if (v > b1) { b2 = b1; b1 = v; bg = g; }
            else if (v > b2) b2 = v;
        }
        sbg[tid] = bg;
        sloff[tid] = atomicAdd(&scnt[bg], 1);
        if (b1 - b2 < THR1) g_fix[atomicAdd(&g_nfix, 1)] = token0 + tid;
    }
    __syncthreads();
    if (tid < GN) sbase[tid] = atomicAdd(&g_cnt[tid], scnt[tid]);
    __syncthreads();
    if (tid < TOKT) g_bucket[sbg[tid]][sbase[sbg[tid]] + sloff[tid]] = token0 + tid;
}

// ---------------- phase 2: per-group expert GEMM + epilogue --------------------
__global__ void __launch_bounds__(TPB) phase2_kernel(
    const float* __restrict__ hs, float* __restrict__ out)
{
    extern __shared__ char smem[];
    float (*sbuf)[BUFW] = reinterpret_cast<float(*)[BUFW]>(smem);
    const u32 mb = (u32)__cvta_generic_to_shared(smem) + SBUF_BYTES;
    int* stok = (int*)(smem + SBUF_BYTES + 64);

    const int tid = threadIdx.x;
    const int g = blockIdx.x;
    const int cnt = g_cnt[g];
    const float* wimg = g_w2 + (size_t)g * (NCHUNK * WCH);
    const size_t OSEL = (size_t)BT * EN, OWGT = OSEL + BT;

    barriers_setup(mb, tid);
    __syncthreads();

    int phf[2] = {0, 0}, phe[2] = {0, 0};

    for (int tile = blockIdx.y; tile * TOKT < cnt; tile += gridDim.y) {
        __syncthreads();
        if (tid < TOKT) {
            int i = tile * TOKT + tid;
            stok[tid] = (i < cnt) ? g_bucket[g][i] : -1;
        }
        __syncthreads();

        float acc[4];
        tile_mma(hs, wimg, P2Tok{stok}, sbuf, mb, acc, phf, phe);

        float* sC = &sbuf[0][0];
        stage_c(sC, acc);
        __syncthreads();

        if (tid < TOKT && stok[tid] >= 0) {
            const float* row = sC + tid * 18;
            float m1 = row[0], m2 = -1e30f; int bi = 0;
#pragma unroll
            for (int e = 1; e < EPG; e++) {
                float v = row[e];
                if (v > m1) { m2 = m1; m1 = v; bi = e; }
                else if (v > m2) m2 = v;
            }
            float s = 0.f;
#pragma unroll
            for (int e = 0; e < EPG; e++) s += expf(row[e] - m1);
            int token = stok[tid];
            out[OSEL + token] = (float)(g * EPG + bi);
            out[OWGT + token] = 1.0f / s;
            if (m1 - m2 < THR2) g_fix[atomicAdd(&g_nfix, 1)] = token;
        }
        __syncthreads();

        if (tid < 256) {
            const int slot0 = tid >> 6, th = tid & 63;
#pragma unroll 4
            for (int p = 0; p < 16; p++) {
                int slot = p * 4 + slot0;
                int token = stok[slot];
                if (token >= 0) {
                    float4 v = make_float4(0.f, 0.f, 0.f, 0.f);
                    if ((th >> 2) == g) {
                        const float* row = sC + slot * 18 + (th & 3) * 4;
                        v = make_float4(row[0], row[1], row[2], row[3]);
                    }
                    *(float4*)&out[(size_t)token * EN + th * 4] = v;
                }
            }
        }
    }
}

// ---------------- exact fp32 fixup ----------------------------------------------
__global__ void __launch_bounds__(512) fixup_kernel(
    const float* __restrict__ hs, const float* __restrict__ gw,
    const float* __restrict__ ew, float* __restrict__ out)
{
    __shared__ float sg[GN], se[EPG];
    __shared__ int sbg_s;
    const int tid = threadIdx.x;
    const int wid = tid >> 5, lane = tid & 31;
    const size_t OSEL = (size_t)BT * EN, OWGT = OSEL + BT;
    const int n = g_nfix;

    for (int i = blockIdx.x; i < n; i += gridDim.x) {
        const int token = g_fix[i];
        const float4* x = (const float4*)(hs + (size_t)token * HD);
        {
            const float4* w = (const float4*)(gw + (size_t)wid * HD);
            float s = 0.f;
#pragma unroll 8
            for (int j = lane; j < HD / 4; j += 32) {
                float4 a = x[j], b = w[j];
                s += a.x * b.x + a.y * b.y + a.z * b.z + a.w * b.w;
            }
#pragma unroll
            for (int o = 16; o; o >>= 1) s += __shfl_xor_sync(0xFFFFFFFF, s, o);
            if (lane == 0) sg[wid] = s;
        }
        __syncthreads();
        if (tid == 0) {
            float best = sg[0]; int bg = 0;
#pragma unroll
            for (int g = 1; g < GN; g++) if (sg[g] > best) { best = sg[g]; bg = g; }
            sbg_s = bg;
        }
        __syncthreads();
        const int bg = sbg_s;
        {
            const float4* w = (const float4*)(ew + (size_t)(bg * EPG + wid) * HD);
            float s = 0.f;
#pragma unroll 8
            for (int j = lane; j < HD / 4; j += 32) {
                float4 a = x[j], b = w[j];
                s += a.x * b.x + a.y * b.y + a.z * b.z + a.w * b.w;
            }
#pragma unroll
            for (int o = 16; o; o >>= 1) s += __shfl_xor_sync(0xFFFFFFFF, s, o);
            if (lane == 0) se[wid] = s;
        }
        __syncthreads();
        if (tid == 0) {
            float m = se[0]; int bi = 0;
#pragma unroll
            for (int e = 1; e < EPG; e++) if (se[e] > m) { m = se[e]; bi = e; }
            float s = 0.f;
#pragma unroll
            for (int e = 0; e < EPG; e++) s += expf(se[e] - m);
            out[OSEL + token] = (float)(bg * EPG + bi);
            out[OWGT + token] = 1.0f / s;
        }
        if (tid < 64) {
            float4 v = make_float4(0.f, 0.f, 0.f, 0.f);
            if ((tid >> 2) == bg) {
                int lo = (tid & 3) * 4;
                v = make_float4(se[lo], se[lo + 1], se[lo + 2], se[lo + 3]);
            }
            *(float4*)&out[(size_t)token * EN + tid * 4] = v;
        }
        __syncthreads();
    }
}

extern "C" void kernel_launch(void* const* d_in, const int* in_sizes, int n_in,
                              void* d_out, int out_size) {
    const float* hs = (const float*)d_in[0];   // [32768, 4096]
    const float* gw = (const float*)d_in[1];   // [16, 4096]
    const float* ew = (const float*)d_in[2];   // [16, 16, 4096]
    float* out = (float*)d_out;

    cudaFuncSetAttribute(phase1_kernel,
                         cudaFuncAttributeMaxDynamicSharedMemorySize, SMEM_DYN);
    cudaFuncSetAttribute(phase2_kernel,
                         cudaFuncAttributeMaxDynamicSharedMemorySize, SMEM_DYN);

    prep_kernel<<<1450, 256>>>(gw, ew);
    phase1_kernel<<<BT / TOKT, TPB, SMEM_DYN>>>(hs);
    phase2_kernel<<<dim3(GN, P2Y), TPB, SMEM_DYN>>>(hs, out);
    fixup_kernel<<<256, 512>>>(hs, gw, ew, out);
}